// round 16
// baseline (speedup 1.0000x reference)
#include <cuda_runtime.h>
#include <cuda_fp16.h>

#define N_NODES 50000
#define E_EDGES 800000
#define NIN     128
#define HC      128
#define ED      44
#define NHEAD   4
#define SCAN_B  196   // ceil(N_NODES/256)

#define NSTR 136
#define ASTR 72
#define WSTR 136

// ----------------------------- scratch (static device globals) ---------------
__device__ __half g_qh  [N_NODES * HC];
__device__ __half g_kh  [N_NODES * HC];
__device__ __half g_vh  [N_NODES * HC];
__device__ __half g_skip[N_NODES * HC];
__device__ __half g_e   [E_EDGES * HC];      // e = edge_attr @ We, edge order
__device__ __half g_wh  [4 * 128 * NSTR];    // node weights, fp16 padded layout
__device__ __half g_weh [48 * WSTR];         // We, fp16 padded (rows 44..47 zero)
__device__ int    g_count[N_NODES];
__device__ int    g_cur  [N_NODES];
__device__ int    g_off  [N_NODES + 1];
__device__ int    g_elist[E_EDGES];          // CSR edge list (by dst)
__device__ int    g_srcs [E_EDGES];          // src node per CSR slot
__device__ int    g_bsum [SCAN_B];
__device__ int    g_boff [SCAN_B];
__device__ int    g_is64;

// ----------------------------- mma helpers -----------------------------------
__device__ __forceinline__ unsigned smem_u32(const void* p)
{
    return (unsigned)__cvta_generic_to_shared(p);
}
__device__ __forceinline__ void ldsm_x4(unsigned addr, unsigned& r0, unsigned& r1,
                                        unsigned& r2, unsigned& r3)
{
    asm volatile("ldmatrix.sync.aligned.m8n8.x4.shared.b16 {%0,%1,%2,%3}, [%4];"
                 : "=r"(r0), "=r"(r1), "=r"(r2), "=r"(r3) : "r"(addr));
}
__device__ __forceinline__ void ldsm_x4_t(unsigned addr, unsigned& r0, unsigned& r1,
                                          unsigned& r2, unsigned& r3)
{
    asm volatile("ldmatrix.sync.aligned.m8n8.x4.trans.shared.b16 {%0,%1,%2,%3}, [%4];"
                 : "=r"(r0), "=r"(r1), "=r"(r2), "=r"(r3) : "r"(addr));
}
__device__ __forceinline__ void mma16816(float* c, unsigned a0, unsigned a1,
                                         unsigned a2, unsigned a3,
                                         unsigned b0, unsigned b1)
{
    asm volatile(
        "mma.sync.aligned.m16n8k16.row.col.f32.f16.f16.f32 "
        "{%0,%1,%2,%3}, {%4,%5,%6,%7}, {%8,%9}, {%0,%1,%2,%3};"
        : "+f"(c[0]), "+f"(c[1]), "+f"(c[2]), "+f"(c[3])
        : "r"(a0), "r"(a1), "r"(a2), "r"(a3), "r"(b0), "r"(b1));
}

// ----------------------------- dtype helpers ----------------------------------
__device__ __forceinline__ int ld_src(const void* ei, int e, int is64)
{
    return is64 ? (int)((const long long*)ei)[e] : ((const int*)ei)[e];
}
__device__ __forceinline__ int ld_dst(const void* ei, int e, int is64)
{
    return is64 ? (int)((const long long*)ei)[E_EDGES + e]
                : ((const int*)ei)[E_EDGES + e];
}

// ----------------------------- weight prep (one pass) --------------------------
__global__ void prep_weights_kernel(const float* __restrict__ Wq,
                                    const float* __restrict__ Wk,
                                    const float* __restrict__ Wv,
                                    const float* __restrict__ Wsk,
                                    const float* __restrict__ We)
{
    int stride = gridDim.x * blockDim.x;
    int tid = blockIdx.x * blockDim.x + threadIdx.x;
    const float* Ws[4] = {Wq, Wk, Wv, Wsk};
    for (int i = tid; i < 4 * 128 * 128; i += stride) {
        int p = i >> 14, rem = i & 16383;
        int r = rem >> 7, c = rem & 127;
        g_wh[p * 128 * NSTR + r * NSTR + c] = __float2half(Ws[p][r * 128 + c]);
    }
    for (int i = tid; i < 48 * 128; i += stride) {
        int r = i >> 7, c = i & 127;
        float v = (r < ED) ? We[r * 128 + c] : 0.f;
        g_weh[r * WSTR + c] = __float2half(v);
    }
}

// ----------------------------- CSR build -------------------------------------
__global__ void detect_zero_kernel(const int* __restrict__ w)
{
    int i = blockIdx.x * blockDim.x + threadIdx.x;
    if (i < N_NODES) g_count[i] = 0;

    if (blockIdx.x == 0) {
        __shared__ int s[256];
        int t = threadIdx.x;
        int acc = 0;
        for (int j = t; j < 8192; j += 256) acc |= w[2 * j + 1];
        s[t] = acc;
        __syncthreads();
        for (int step = 128; step > 0; step >>= 1) {
            if (t < step) s[t] |= s[t + step];
            __syncthreads();
        }
        if (t == 0) g_is64 = (s[0] == 0) ? 1 : 0;
    }
}

__global__ void count_kernel(const void* __restrict__ ei)
{
    int e = blockIdx.x * blockDim.x + threadIdx.x;
    int dst = ld_dst(ei, e, g_is64);
    if (dst >= 0 && dst < N_NODES) atomicAdd(&g_count[dst], 1);
}

__device__ __forceinline__ int block_incl_scan(int v, int* ws)
{
    const int lane = threadIdx.x & 31, wid = threadIdx.x >> 5;
    int incl = v;
    #pragma unroll
    for (int s = 1; s < 32; s <<= 1) {
        int o = __shfl_up_sync(0xffffffffu, incl, s);
        if (lane >= s) incl += o;
    }
    if (lane == 31) ws[wid] = incl;
    __syncthreads();
    if (wid == 0) {
        int wv = (lane < 8) ? ws[lane] : 0;
        int wi = wv;
        #pragma unroll
        for (int s = 1; s < 8; s <<= 1) {
            int o = __shfl_up_sync(0xffffffffu, wi, s);
            if (lane >= s) wi += o;
        }
        if (lane < 8) ws[lane] = wi - wv;
    }
    __syncthreads();
    return ws[wid] + incl;
}

__global__ void scan1_kernel()
{
    __shared__ int ws[8];
    int idx = blockIdx.x * 256 + threadIdx.x;
    int v = (idx < N_NODES) ? g_count[idx] : 0;
    int incl = block_incl_scan(v, ws);
    if (threadIdx.x == 255) g_bsum[blockIdx.x] = incl;
}

__global__ void scan2_kernel()
{
    __shared__ int ws[8];
    int t = threadIdx.x;
    int v = (t < SCAN_B) ? g_bsum[t] : 0;
    int incl = block_incl_scan(v, ws);
    if (t < SCAN_B) g_boff[t] = incl - v;
    if (t == SCAN_B - 1) g_off[N_NODES] = incl;
}

__global__ void scan3_kernel()
{
    __shared__ int ws[8];
    int idx = blockIdx.x * 256 + threadIdx.x;
    int v = (idx < N_NODES) ? g_count[idx] : 0;
    int incl = block_incl_scan(v, ws);
    if (idx < N_NODES) {
        int off = g_boff[blockIdx.x] + incl - v;
        g_off[idx] = off;
        g_cur[idx] = off;
    }
}

__global__ void fill_kernel(const void* __restrict__ ei)
{
    int e = blockIdx.x * blockDim.x + threadIdx.x;
    int is64 = g_is64;
    int dst = ld_dst(ei, e, is64);
    int src = ld_src(ei, e, is64);
    src = min(max(src, 0), N_NODES - 1);
    if (dst >= 0 && dst < N_NODES) {
        int pos = atomicAdd(&g_cur[dst], 1);
        g_elist[pos] = e;
        g_srcs[pos] = src;
    }
}

// ----------------------------- node projections (HMMA, flattened) -------------
// gridDim.y = 4 (projection), 64-node tiles. Warp w: rows (w>>1)*16,
// cols (w&1)*64 -> acc 32 floats, smem 52.2 KB -> 4 CTAs/SM at 64-reg budget.
__global__ void __launch_bounds__(256, 4)
node_proj_kernel(const float* __restrict__ x,
                 const float* __restrict__ bq, const float* __restrict__ bk,
                 const float* __restrict__ bv, const float* __restrict__ bsk)
{
    extern __shared__ __half smh[];
    __half* sX = smh;                 // 64 x NSTR (reused as output staging)
    __half* sW = smh + 64 * NSTR;     // 128 x NSTR
    const int tid = threadIdx.x;
    const int warp = tid >> 5, lane = tid & 31;
    const int p = blockIdx.y;
    const int n0 = blockIdx.x * 64;

    // x tile: 64 rows x 128 cols, fp32 -> fp16
    for (int i = tid * 4; i < 64 * 128; i += 256 * 4) {
        int r = i >> 7, c = i & 127;
        int node = n0 + r;
        float4 val = make_float4(0.f, 0.f, 0.f, 0.f);
        if (node < N_NODES) val = *(const float4*)(x + node * NIN + c);
        __half2 h0 = __floats2half2_rn(val.x, val.y);
        __half2 h1 = __floats2half2_rn(val.z, val.w);
        uint2 pk; *(__half2*)&pk.x = h0; *(__half2*)&pk.y = h1;
        *(uint2*)(sX + r * NSTR + c) = pk;
    }
    // W_p: 128 rows x 16 uint4 from pre-converted image
    {
        const __half* Wh = g_wh + p * 128 * NSTR;
        for (int i = tid; i < 2048; i += 256) {
            int r = i >> 4, ch = i & 15;
            *(uint4*)(sW + r * NSTR + ch * 8) =
                *(const uint4*)(Wh + r * NSTR + ch * 8);
        }
    }
    __syncthreads();

    const int row0 = (warp >> 1) * 16;     // 0,16,32,48
    const int nc0  = (warp & 1) * 64;      // col half
    const int dr = lane >> 2;              // 0..7
    const int dc = 2 * (lane & 3);         // 0,2,4,6

    float acc[8][4];
    #pragma unroll
    for (int t = 0; t < 8; ++t)
        #pragma unroll
        for (int j = 0; j < 4; ++j) acc[t][j] = 0.f;

    #pragma unroll
    for (int kc = 0; kc < 8; ++kc) {
        int k0 = kc * 16;
        unsigned a0, a1, a2, a3;
        {
            int r = row0 + (lane & 15);
            int c = k0 + 8 * (lane >> 4);
            ldsm_x4(smem_u32(sX + r * NSTR + c), a0, a1, a2, a3);
        }
        #pragma unroll
        for (int nt = 0; nt < 4; ++nt) {
            int nn = nc0 + nt * 16;
            unsigned b0, b1, b2, b3;
            int r = k0 + (lane & 15);
            int c = nn + 8 * (lane >> 4);
            ldsm_x4_t(smem_u32(sW + r * NSTR + c), b0, b1, b2, b3);
            mma16816(acc[2 * nt],     a0, a1, a2, a3, b0, b1);
            mma16816(acc[2 * nt + 1], a0, a1, a2, a3, b2, b3);
        }
    }
    __syncthreads();                       // done reading sX -> reuse as staging

    const float* bias = (p == 0) ? bq : (p == 1) ? bk : (p == 2) ? bv : bsk;
    #pragma unroll
    for (int t = 0; t < 8; ++t) {
        int c = nc0 + t * 8 + dc;
        float b0v = bias[c], b1v = bias[c + 1];
        *(__half2*)(sX + (row0 + dr) * NSTR + c) =
            __floats2half2_rn(acc[t][0] + b0v, acc[t][1] + b1v);
        *(__half2*)(sX + (row0 + dr + 8) * NSTR + c) =
            __floats2half2_rn(acc[t][2] + b0v, acc[t][3] + b1v);
    }
    __syncthreads();

    __half* O = (p == 0) ? g_qh : (p == 1) ? g_kh : (p == 2) ? g_vh : g_skip;
    for (int i = tid; i < 64 * 16; i += 256) {     // 64 rows x 16 uint4
        int r = i >> 4, ch = i & 15;
        int node = n0 + r;
        if (node < N_NODES)
            *(uint4*)(O + node * HC + ch * 8) =
                *(uint4*)(sX + r * NSTR + ch * 8);
    }
}

// ----------------------------- E1: edge GEMM ----------------------------------
// 2 tiles of 64 edges per block; warp w within a tile: rows (w>>1)*16,
// cols (w&1)*64. 4 CTAs/SM at 64-reg budget.
__global__ void __launch_bounds__(256, 4)
edge_gemm_kernel(const float* __restrict__ edge_attr)
{
    extern __shared__ __half smh[];
    __half* sA  = smh;                         // 64 x ASTR  (K in cols 0..47)
    __half* sWe = smh + 64 * ASTR;             // 48 x WSTR
    __half* sE  = sWe + 48 * WSTR;             // 64 x WSTR
    const int tid = threadIdx.x;
    const int warp = tid >> 5, lane = tid & 31;

    for (int i = tid; i < 48 * 16; i += 256) { // We: 48 rows x 16 uint4 (once)
        int r = i >> 4, ch = i & 15;
        *(uint4*)(sWe + r * WSTR + ch * 8) =
            *(const uint4*)(g_weh + r * WSTR + ch * 8);
    }

    const int row0 = (warp >> 1) * 16;         // 0,16,32,48
    const int nc0  = (warp & 1) * 64;          // col half
    const int dr = lane >> 2;
    const int dc = 2 * (lane & 3);

    #pragma unroll
    for (int it = 0; it < 2; ++it) {
        const int e0 = blockIdx.x * 128 + it * 64;

        for (int i = tid; i < 64 * 11; i += 256) {
            int r = i / 11, q = i - r * 11;
            float4 v = *(const float4*)(edge_attr + (e0 + r) * ED + 4 * q);
            __half2 h0 = __floats2half2_rn(v.x, v.y);
            __half2 h1 = __floats2half2_rn(v.z, v.w);
            uint2 pk; *(__half2*)&pk.x = h0; *(__half2*)&pk.y = h1;
            *(uint2*)(sA + r * ASTR + 4 * q) = pk;
        }
        for (int i = tid; i < 64; i += 256) {
            *(uint2*)(sA + i * ASTR + 44) = make_uint2(0u, 0u);
        }
        __syncthreads();   // sA (and, iter 0, sWe) ready; prior sE reads done

        float acc[8][4];
        #pragma unroll
        for (int t = 0; t < 8; ++t)
            #pragma unroll
            for (int j = 0; j < 4; ++j) acc[t][j] = 0.f;

        #pragma unroll
        for (int kc = 0; kc < 3; ++kc) {
            int k0 = kc * 16;
            unsigned a0, a1, a2, a3;
            {
                int r = row0 + (lane & 15);
                int c = k0 + 8 * (lane >> 4);
                ldsm_x4(smem_u32(sA + r * ASTR + c), a0, a1, a2, a3);
            }
            #pragma unroll
            for (int nt = 0; nt < 4; ++nt) {
                int nn = nc0 + nt * 16;
                unsigned b0, b1, b2, b3;
                int r = k0 + (lane & 15);
                int c = nn + 8 * (lane >> 4);
                ldsm_x4_t(smem_u32(sWe + r * WSTR + c), b0, b1, b2, b3);
                mma16816(acc[2 * nt],     a0, a1, a2, a3, b0, b1);
                mma16816(acc[2 * nt + 1], a0, a1, a2, a3, b2, b3);
            }
        }

        #pragma unroll
        for (int t = 0; t < 8; ++t) {
            int c = nc0 + t * 8 + dc;
            *(__half2*)(sE + (row0 + dr) * WSTR + c) =
                __floats2half2_rn(acc[t][0], acc[t][1]);
            *(__half2*)(sE + (row0 + dr + 8) * WSTR + c) =
                __floats2half2_rn(acc[t][2], acc[t][3]);
        }
        __syncthreads();   // sE complete (rows written by 2 warps each)

        for (int i = tid; i < 64 * 16; i += 256) {
            int r = i >> 4, ch = i & 15;
            *(uint4*)(g_e + (e0 + r) * HC + ch * 8) =
                *(uint4*)(sE + r * WSTR + ch * 8);
        }
    }
}

// ----------------------------- E2: fused gather + softmax + aggregate ---------
// One warp per dst node; lane l owns cols 4l..4l+3. NO launch_bounds: the hot
// loop keeps ~55 live values (12 uint2 gather buffers + q + softmax state);
// the previous (256,8) forced a 32-reg budget -> spills/serialized loads.
__global__ void
agg_fused_kernel(float* __restrict__ out)
{
    const int n = (blockIdx.x * blockDim.x + threadIdx.x) >> 5; // exactly N warps
    const int l = threadIdx.x & 31;
    const int c0 = 4 * l;
    const float isc = 0.17677669529663689f;    // 1/sqrt(32)

    const int beg = g_off[n], end = g_off[n + 1];

    uint2 qr = *(const uint2*)(g_qh + n * HC + c0);
    float2 q01 = __half22float2(*(__half2*)&qr.x);
    float2 q23 = __half22float2(*(__half2*)&qr.y);

    float m = -1e30f, den = 0.f;
    float acc0 = 0.f, acc1 = 0.f, acc2 = 0.f, acc3 = 0.f;

    for (int i = beg; i < end; i += 2) {
        const bool has2 = (i + 1 < end);
        int ib = has2 ? (i + 1) : i;
        int ea = g_elist[i];
        int eb = g_elist[ib];
        int sa = g_srcs[i];
        int sb = g_srcs[ib];

        // issue all 6 gathers before consuming
        uint2 er_a = *(const uint2*)(g_e  + ea * HC + c0);
        uint2 kr_a = *(const uint2*)(g_kh + sa * HC + c0);
        uint2 vr_a = *(const uint2*)(g_vh + sa * HC + c0);
        uint2 er_b = *(const uint2*)(g_e  + eb * HC + c0);
        uint2 kr_b = *(const uint2*)(g_kh + sb * HC + c0);
        uint2 vr_b = *(const uint2*)(g_vh + sb * HC + c0);

        float2 ea01 = __half22float2(*(__half2*)&er_a.x);
        float2 ea23 = __half22float2(*(__half2*)&er_a.y);
        float2 ka01 = __half22float2(*(__half2*)&kr_a.x);
        float2 ka23 = __half22float2(*(__half2*)&kr_a.y);
        float2 va01 = __half22float2(*(__half2*)&vr_a.x);
        float2 va23 = __half22float2(*(__half2*)&vr_a.y);
        float2 eb01 = __half22float2(*(__half2*)&er_b.x);
        float2 eb23 = __half22float2(*(__half2*)&er_b.y);
        float2 kb01 = __half22float2(*(__half2*)&kr_b.x);
        float2 kb23 = __half22float2(*(__half2*)&kr_b.y);
        float2 vb01 = __half22float2(*(__half2*)&vr_b.x);
        float2 vb23 = __half22float2(*(__half2*)&vr_b.y);

        float pa = q01.x * (ka01.x + ea01.x) + q01.y * (ka01.y + ea01.y)
                 + q23.x * (ka23.x + ea23.x) + q23.y * (ka23.y + ea23.y);
        float pb = q01.x * (kb01.x + eb01.x) + q01.y * (kb01.y + eb01.y)
                 + q23.x * (kb23.x + eb23.x) + q23.y * (kb23.y + eb23.y);

        pa += __shfl_xor_sync(0xffffffffu, pa, 1);
        pb += __shfl_xor_sync(0xffffffffu, pb, 1);
        pa += __shfl_xor_sync(0xffffffffu, pa, 2);
        pb += __shfl_xor_sync(0xffffffffu, pb, 2);
        pa += __shfl_xor_sync(0xffffffffu, pa, 4);
        pb += __shfl_xor_sync(0xffffffffu, pb, 4);

        float aa = pa * isc;
        float ab = has2 ? (pb * isc) : -1e30f;

        float nm = fmaxf(m, fmaxf(aa, ab));
        float sc = __expf(m - nm);
        float wa = __expf(aa - nm);
        float wb = __expf(ab - nm);           // 0 when !has2
        den = den * sc + wa + wb;
        acc0 = acc0 * sc + wa * (va01.x + ea01.x) + wb * (vb01.x + eb01.x);
        acc1 = acc1 * sc + wa * (va01.y + ea01.y) + wb * (vb01.y + eb01.y);
        acc2 = acc2 * sc + wa * (va23.x + ea23.x) + wb * (vb23.x + eb23.x);
        acc3 = acc3 * sc + wa * (va23.y + ea23.y) + wb * (vb23.y + eb23.y);
        m = nm;
    }

    float inv = 1.f / (den + 1e-16f);
    uint2 skr = *(const uint2*)(g_skip + n * HC + c0);
    float2 s01 = __half22float2(*(__half2*)&skr.x);
    float2 s23 = __half22float2(*(__half2*)&skr.y);
    *(float4*)(out + n * HC + c0) =
        make_float4(acc0 * inv + s01.x, acc1 * inv + s01.y,
                    acc2 * inv + s23.x, acc3 * inv + s23.y);
}

// ----------------------------- launch -----------------------------------------
// edge_gemm at #4 to re-verify the 2-tile amortization under the capture window.
extern "C" void kernel_launch(void* const* d_in, const int* in_sizes, int n_in,
                              void* d_out, int out_size)
{
    const float* x   = (const float*)d_in[0];
    const void*  ei  = d_in[1];
    const float* ea  = (const float*)d_in[2];
    const float* Wq  = (const float*)d_in[3];
    const float* bq  = (const float*)d_in[4];
    const float* Wk  = (const float*)d_in[5];
    const float* bk  = (const float*)d_in[6];
    const float* Wv  = (const float*)d_in[7];
    const float* bv  = (const float*)d_in[8];
    const float* We  = (const float*)d_in[9];
    const float* Wsk = (const float*)d_in[10];
    const float* bsk = (const float*)d_in[11];
    float* out = (float*)d_out;

    const int smem_node = (64 * NSTR + 128 * NSTR) * 2;             // 52.2 KB
    const int smem_edge = (64 * ASTR + 48 * WSTR + 64 * WSTR) * 2;  // 38.8 KB
    cudaFuncSetAttribute(node_proj_kernel,
                         cudaFuncAttributeMaxDynamicSharedMemorySize, smem_node);
    cudaFuncSetAttribute(edge_gemm_kernel,
                         cudaFuncAttributeMaxDynamicSharedMemorySize, smem_edge);

    prep_weights_kernel<<<128, 256>>>(Wq, Wk, Wv, Wsk, We);         // #1
    detect_zero_kernel<<<SCAN_B, 256>>>((const int*)ei);            // #2
    count_kernel<<<E_EDGES / 256, 256>>>(ei);                       // #3
    edge_gemm_kernel<<<E_EDGES / 128, 256, smem_edge>>>(ea);        // #4 (profiled)
    dim3 npgrid((N_NODES + 63) / 64, 4);
    node_proj_kernel<<<npgrid, 256, smem_node>>>(                   // #5
        x, bq, bk, bv, bsk);
    scan1_kernel<<<SCAN_B, 256>>>();                                // #6
    scan2_kernel<<<1, 256>>>();                                     // #7
    scan3_kernel<<<SCAN_B, 256>>>();                                // #8
    fill_kernel<<<E_EDGES / 256, 256>>>(ei);                        // #9
    agg_fused_kernel<<<(N_NODES * 32) / 256, 256>>>(out);           // #10
}

// round 17
// speedup vs baseline: 1.0294x; 1.0294x over previous
#include <cuda_runtime.h>
#include <cuda_fp16.h>

#define N_NODES 50000
#define E_EDGES 800000
#define NIN     128
#define HC      128
#define ED      44
#define NHEAD   4
#define SCAN_B  196    // ceil(N_NODES/256)
#define NP_TILES 782   // ceil(N_NODES/64)
#define NP_BLOCKS (NP_TILES * 4)
#define EG_BLOCKS (E_EDGES / 128)

#define NSTR 136
#define ASTR 72
#define WSTR 136

// ----------------------------- scratch (static device globals) ---------------
__device__ __half g_qh  [N_NODES * HC];
__device__ __half g_kh  [N_NODES * HC];
__device__ __half g_vh  [N_NODES * HC];
__device__ __half g_skip[N_NODES * HC];
__device__ __half g_e   [E_EDGES * HC];      // e = edge_attr @ We, edge order
__device__ __half g_wh  [4 * 128 * NSTR];    // node weights, fp16 padded layout
__device__ __half g_weh [48 * WSTR];         // We, fp16 padded (rows 44..47 zero)
__device__ int    g_count[N_NODES];
__device__ int    g_cur  [N_NODES];
__device__ int    g_off  [N_NODES + 1];
__device__ int    g_elist[E_EDGES];          // CSR edge list (by dst)
__device__ int    g_srcs [E_EDGES];          // src node per CSR slot
__device__ int    g_bsum [SCAN_B];
__device__ int    g_boff [SCAN_B];

// ----------------------------- mma helpers -----------------------------------
__device__ __forceinline__ unsigned smem_u32(const void* p)
{
    return (unsigned)__cvta_generic_to_shared(p);
}
__device__ __forceinline__ void ldsm_x4(unsigned addr, unsigned& r0, unsigned& r1,
                                        unsigned& r2, unsigned& r3)
{
    asm volatile("ldmatrix.sync.aligned.m8n8.x4.shared.b16 {%0,%1,%2,%3}, [%4];"
                 : "=r"(r0), "=r"(r1), "=r"(r2), "=r"(r3) : "r"(addr));
}
__device__ __forceinline__ void ldsm_x4_t(unsigned addr, unsigned& r0, unsigned& r1,
                                          unsigned& r2, unsigned& r3)
{
    asm volatile("ldmatrix.sync.aligned.m8n8.x4.trans.shared.b16 {%0,%1,%2,%3}, [%4];"
                 : "=r"(r0), "=r"(r1), "=r"(r2), "=r"(r3) : "r"(addr));
}
__device__ __forceinline__ void mma16816(float* c, unsigned a0, unsigned a1,
                                         unsigned a2, unsigned a3,
                                         unsigned b0, unsigned b1)
{
    asm volatile(
        "mma.sync.aligned.m16n8k16.row.col.f32.f16.f16.f32 "
        "{%0,%1,%2,%3}, {%4,%5,%6,%7}, {%8,%9}, {%0,%1,%2,%3};"
        : "+f"(c[0]), "+f"(c[1]), "+f"(c[2]), "+f"(c[3])
        : "r"(a0), "r"(a1), "r"(a2), "r"(a3), "r"(b0), "r"(b1));
}

// ----------------------------- per-block dtype detection ----------------------
// OR of this block's 256 odd 32-bit words of the index buffer. int64 data:
// high words of values < 50000 -> 0. int32 data: node indices, P(all 0) ~ 0.
__device__ __forceinline__ int block_detect_is64(const int* w, int base256)
{
    __shared__ int ws_det[8];
    __shared__ int s_is64;
    const int lane = threadIdx.x & 31, wid = threadIdx.x >> 5;
    int probe = w[2 * (base256 + threadIdx.x) + 1];
    #pragma unroll
    for (int s = 16; s > 0; s >>= 1)
        probe |= __shfl_xor_sync(0xffffffffu, probe, s);
    if (lane == 0) ws_det[wid] = probe;
    __syncthreads();
    if (threadIdx.x == 0) {
        int a = 0;
        #pragma unroll
        for (int j = 0; j < 8; ++j) a |= ws_det[j];
        s_is64 = (a == 0) ? 1 : 0;
    }
    __syncthreads();
    return s_is64;
}

__device__ __forceinline__ int ld_srcv(const void* ei, int e, int is64)
{
    return is64 ? (int)((const long long*)ei)[e] : ((const int*)ei)[e];
}
__device__ __forceinline__ int ld_dstv(const void* ei, int e, int is64)
{
    return is64 ? (int)((const long long*)ei)[E_EDGES + e]
                : ((const int*)ei)[E_EDGES + e];
}

// ----------------------------- weight prep + counter zero ----------------------
__global__ void prep_weights_kernel(const float* __restrict__ Wq,
                                    const float* __restrict__ Wk,
                                    const float* __restrict__ Wv,
                                    const float* __restrict__ Wsk,
                                    const float* __restrict__ We)
{
    int stride = gridDim.x * blockDim.x;
    int tid = blockIdx.x * blockDim.x + threadIdx.x;
    const float* Ws[4] = {Wq, Wk, Wv, Wsk};
    for (int i = tid; i < 4 * 128 * 128; i += stride) {
        int p = i >> 14, rem = i & 16383;
        int r = rem >> 7, c = rem & 127;
        g_wh[p * 128 * NSTR + r * NSTR + c] = __float2half(Ws[p][r * 128 + c]);
    }
    for (int i = tid; i < 48 * 128; i += stride) {
        int r = i >> 7, c = i & 127;
        float v = (r < ED) ? We[r * 128 + c] : 0.f;
        g_weh[r * WSTR + c] = __float2half(v);
    }
    for (int i = tid; i < N_NODES; i += stride) g_count[i] = 0;
}

// ----------------------------- CSR build -------------------------------------
__global__ void count_kernel(const int* __restrict__ w)
{
    int is64 = block_detect_is64(w, blockIdx.x * 256);
    int e = blockIdx.x * 256 + threadIdx.x;
    int dst = ld_dstv(w, e, is64);
    if (dst >= 0 && dst < N_NODES) atomicAdd(&g_count[dst], 1);
}

__device__ __forceinline__ int block_incl_scan(int v, int* ws)
{
    const int lane = threadIdx.x & 31, wid = threadIdx.x >> 5;
    int incl = v;
    #pragma unroll
    for (int s = 1; s < 32; s <<= 1) {
        int o = __shfl_up_sync(0xffffffffu, incl, s);
        if (lane >= s) incl += o;
    }
    if (lane == 31) ws[wid] = incl;
    __syncthreads();
    if (wid == 0) {
        int wv = (lane < 8) ? ws[lane] : 0;
        int wi = wv;
        #pragma unroll
        for (int s = 1; s < 8; s <<= 1) {
            int o = __shfl_up_sync(0xffffffffu, wi, s);
            if (lane >= s) wi += o;
        }
        if (lane < 8) ws[lane] = wi - wv;
    }
    __syncthreads();
    return ws[wid] + incl;
}

__global__ void scan1_kernel()
{
    __shared__ int ws[8];
    int idx = blockIdx.x * 256 + threadIdx.x;
    int v = (idx < N_NODES) ? g_count[idx] : 0;
    int incl = block_incl_scan(v, ws);
    if (threadIdx.x == 255) g_bsum[blockIdx.x] = incl;
}

__global__ void scan2_kernel()
{
    __shared__ int ws[8];
    int t = threadIdx.x;
    int v = (t < SCAN_B) ? g_bsum[t] : 0;
    int incl = block_incl_scan(v, ws);
    if (t < SCAN_B) g_boff[t] = incl - v;
    if (t == SCAN_B - 1) g_off[N_NODES] = incl;
}

__global__ void scan3_kernel()
{
    __shared__ int ws[8];
    int idx = blockIdx.x * 256 + threadIdx.x;
    int v = (idx < N_NODES) ? g_count[idx] : 0;
    int incl = block_incl_scan(v, ws);
    if (idx < N_NODES) {
        int off = g_boff[blockIdx.x] + incl - v;
        g_off[idx] = off;
        g_cur[idx] = off;
    }
}

__global__ void fill_kernel(const int* __restrict__ w)
{
    int is64 = block_detect_is64(w, blockIdx.x * 256);
    int e = blockIdx.x * 256 + threadIdx.x;
    int dst = ld_dstv(w, e, is64);
    int src = ld_srcv(w, e, is64);
    src = min(max(src, 0), N_NODES - 1);
    if (dst >= 0 && dst < N_NODES) {
        int pos = atomicAdd(&g_cur[dst], 1);
        g_elist[pos] = e;
        g_srcs[pos] = src;
    }
}

// ----------------------------- fused GEMMs (node proj + edge GEMM) ------------
// Blocks [0, NP_BLOCKS): node projection, p = bid/NP_TILES, 64-node tiles.
// Blocks [NP_BLOCKS, +EG_BLOCKS): edge GEMM, 2 tiles of 64 edges.
// Both: warp w -> rows (w>>1)*16, cols (w&1)*64; 32-float acc; 4 CTAs/SM.
__global__ void __launch_bounds__(256, 4)
gemm_fused_kernel(const float* __restrict__ x,
                  const float* __restrict__ edge_attr,
                  const float* __restrict__ bq, const float* __restrict__ bk,
                  const float* __restrict__ bv, const float* __restrict__ bsk)
{
    extern __shared__ __half smh[];
    const int tid = threadIdx.x;
    const int warp = tid >> 5, lane = tid & 31;
    const int row0 = (warp >> 1) * 16;
    const int nc0  = (warp & 1) * 64;
    const int dr = lane >> 2;
    const int dc = 2 * (lane & 3);

    if (blockIdx.x < NP_BLOCKS) {
        // ------------------ node projection ------------------
        __half* sX = smh;                 // 64 x NSTR (reused as staging)
        __half* sW = smh + 64 * NSTR;     // 128 x NSTR
        const int p = blockIdx.x / NP_TILES;
        const int n0 = (blockIdx.x % NP_TILES) * 64;

        for (int i = tid * 4; i < 64 * 128; i += 256 * 4) {
            int r = i >> 7, c = i & 127;
            int node = n0 + r;
            float4 val = make_float4(0.f, 0.f, 0.f, 0.f);
            if (node < N_NODES) val = *(const float4*)(x + node * NIN + c);
            __half2 h0 = __floats2half2_rn(val.x, val.y);
            __half2 h1 = __floats2half2_rn(val.z, val.w);
            uint2 pk; *(__half2*)&pk.x = h0; *(__half2*)&pk.y = h1;
            *(uint2*)(sX + r * NSTR + c) = pk;
        }
        {
            const __half* Wh = g_wh + p * 128 * NSTR;
            for (int i = tid; i < 2048; i += 256) {
                int r = i >> 4, ch = i & 15;
                *(uint4*)(sW + r * NSTR + ch * 8) =
                    *(const uint4*)(Wh + r * NSTR + ch * 8);
            }
        }
        __syncthreads();

        float acc[8][4];
        #pragma unroll
        for (int t = 0; t < 8; ++t)
            #pragma unroll
            for (int j = 0; j < 4; ++j) acc[t][j] = 0.f;

        #pragma unroll
        for (int kc = 0; kc < 8; ++kc) {
            int k0 = kc * 16;
            unsigned a0, a1, a2, a3;
            {
                int r = row0 + (lane & 15);
                int c = k0 + 8 * (lane >> 4);
                ldsm_x4(smem_u32(sX + r * NSTR + c), a0, a1, a2, a3);
            }
            #pragma unroll
            for (int nt = 0; nt < 4; ++nt) {
                int nn = nc0 + nt * 16;
                unsigned b0, b1, b2, b3;
                int r = k0 + (lane & 15);
                int c = nn + 8 * (lane >> 4);
                ldsm_x4_t(smem_u32(sW + r * NSTR + c), b0, b1, b2, b3);
                mma16816(acc[2 * nt],     a0, a1, a2, a3, b0, b1);
                mma16816(acc[2 * nt + 1], a0, a1, a2, a3, b2, b3);
            }
        }
        __syncthreads();                   // done reading sX -> staging

        const float* bias = (p == 0) ? bq : (p == 1) ? bk : (p == 2) ? bv : bsk;
        #pragma unroll
        for (int t = 0; t < 8; ++t) {
            int c = nc0 + t * 8 + dc;
            float b0v = bias[c], b1v = bias[c + 1];
            *(__half2*)(sX + (row0 + dr) * NSTR + c) =
                __floats2half2_rn(acc[t][0] + b0v, acc[t][1] + b1v);
            *(__half2*)(sX + (row0 + dr + 8) * NSTR + c) =
                __floats2half2_rn(acc[t][2] + b0v, acc[t][3] + b1v);
        }
        __syncthreads();

        __half* O = (p == 0) ? g_qh : (p == 1) ? g_kh : (p == 2) ? g_vh : g_skip;
        for (int i = tid; i < 64 * 16; i += 256) {
            int r = i >> 4, ch = i & 15;
            int node = n0 + r;
            if (node < N_NODES)
                *(uint4*)(O + node * HC + ch * 8) =
                    *(uint4*)(sX + r * NSTR + ch * 8);
        }
    } else {
        // ------------------ edge GEMM ------------------
        __half* sA  = smh;                         // 64 x ASTR
        __half* sWe = smh + 64 * ASTR;             // 48 x WSTR
        __half* sE  = sWe + 48 * WSTR;             // 64 x WSTR
        const int bid = blockIdx.x - NP_BLOCKS;

        for (int i = tid; i < 48 * 16; i += 256) {
            int r = i >> 4, ch = i & 15;
            *(uint4*)(sWe + r * WSTR + ch * 8) =
                *(const uint4*)(g_weh + r * WSTR + ch * 8);
        }

        #pragma unroll
        for (int it = 0; it < 2; ++it) {
            const int e0 = bid * 128 + it * 64;

            for (int i = tid; i < 64 * 11; i += 256) {
                int r = i / 11, q = i - r * 11;
                float4 v = *(const float4*)(edge_attr + (e0 + r) * ED + 4 * q);
                __half2 h0 = __floats2half2_rn(v.x, v.y);
                __half2 h1 = __floats2half2_rn(v.z, v.w);
                uint2 pk; *(__half2*)&pk.x = h0; *(__half2*)&pk.y = h1;
                *(uint2*)(sA + r * ASTR + 4 * q) = pk;
            }
            for (int i = tid; i < 64; i += 256)
                *(uint2*)(sA + i * ASTR + 44) = make_uint2(0u, 0u);
            __syncthreads();

            float acc[8][4];
            #pragma unroll
            for (int t = 0; t < 8; ++t)
                #pragma unroll
                for (int j = 0; j < 4; ++j) acc[t][j] = 0.f;

            #pragma unroll
            for (int kc = 0; kc < 3; ++kc) {
                int k0 = kc * 16;
                unsigned a0, a1, a2, a3;
                {
                    int r = row0 + (lane & 15);
                    int c = k0 + 8 * (lane >> 4);
                    ldsm_x4(smem_u32(sA + r * ASTR + c), a0, a1, a2, a3);
                }
                #pragma unroll
                for (int nt = 0; nt < 4; ++nt) {
                    int nn = nc0 + nt * 16;
                    unsigned b0, b1, b2, b3;
                    int r = k0 + (lane & 15);
                    int c = nn + 8 * (lane >> 4);
                    ldsm_x4_t(smem_u32(sWe + r * WSTR + c), b0, b1, b2, b3);
                    mma16816(acc[2 * nt],     a0, a1, a2, a3, b0, b1);
                    mma16816(acc[2 * nt + 1], a0, a1, a2, a3, b2, b3);
                }
            }

            #pragma unroll
            for (int t = 0; t < 8; ++t) {
                int c = nc0 + t * 8 + dc;
                *(__half2*)(sE + (row0 + dr) * WSTR + c) =
                    __floats2half2_rn(acc[t][0], acc[t][1]);
                *(__half2*)(sE + (row0 + dr + 8) * WSTR + c) =
                    __floats2half2_rn(acc[t][2], acc[t][3]);
            }
            __syncthreads();

            for (int i = tid; i < 64 * 16; i += 256) {
                int r = i >> 4, ch = i & 15;
                *(uint4*)(g_e + (e0 + r) * HC + ch * 8) =
                    *(uint4*)(sE + r * WSTR + ch * 8);
            }
        }
    }
}

// ----------------------------- E2: fused gather + softmax + aggregate ---------
// One warp per dst node; lane l owns cols 4l..4l+3. (R15-best config.)
__global__ void __launch_bounds__(256, 8)
agg_fused_kernel(float* __restrict__ out)
{
    const int n = (blockIdx.x * blockDim.x + threadIdx.x) >> 5; // exactly N warps
    const int l = threadIdx.x & 31;
    const int c0 = 4 * l;
    const float isc = 0.17677669529663689f;    // 1/sqrt(32)

    const int beg = g_off[n], end = g_off[n + 1];

    uint2 qr = *(const uint2*)(g_qh + n * HC + c0);
    float2 q01 = __half22float2(*(__half2*)&qr.x);
    float2 q23 = __half22float2(*(__half2*)&qr.y);

    float m = -1e30f, den = 0.f;
    float acc0 = 0.f, acc1 = 0.f, acc2 = 0.f, acc3 = 0.f;

    for (int i = beg; i < end; i += 2) {
        const bool has2 = (i + 1 < end);
        int ib = has2 ? (i + 1) : i;
        int ea = g_elist[i];
        int eb = g_elist[ib];
        int sa = g_srcs[i];
        int sb = g_srcs[ib];

        uint2 er_a = *(const uint2*)(g_e  + ea * HC + c0);
        uint2 kr_a = *(const uint2*)(g_kh + sa * HC + c0);
        uint2 vr_a = *(const uint2*)(g_vh + sa * HC + c0);
        uint2 er_b = *(const uint2*)(g_e  + eb * HC + c0);
        uint2 kr_b = *(const uint2*)(g_kh + sb * HC + c0);
        uint2 vr_b = *(const uint2*)(g_vh + sb * HC + c0);

        float2 ea01 = __half22float2(*(__half2*)&er_a.x);
        float2 ea23 = __half22float2(*(__half2*)&er_a.y);
        float2 ka01 = __half22float2(*(__half2*)&kr_a.x);
        float2 ka23 = __half22float2(*(__half2*)&kr_a.y);
        float2 va01 = __half22float2(*(__half2*)&vr_a.x);
        float2 va23 = __half22float2(*(__half2*)&vr_a.y);
        float2 eb01 = __half22float2(*(__half2*)&er_b.x);
        float2 eb23 = __half22float2(*(__half2*)&er_b.y);
        float2 kb01 = __half22float2(*(__half2*)&kr_b.x);
        float2 kb23 = __half22float2(*(__half2*)&kr_b.y);
        float2 vb01 = __half22float2(*(__half2*)&vr_b.x);
        float2 vb23 = __half22float2(*(__half2*)&vr_b.y);

        float pa = q01.x * (ka01.x + ea01.x) + q01.y * (ka01.y + ea01.y)
                 + q23.x * (ka23.x + ea23.x) + q23.y * (ka23.y + ea23.y);
        float pb = q01.x * (kb01.x + eb01.x) + q01.y * (kb01.y + eb01.y)
                 + q23.x * (kb23.x + eb23.x) + q23.y * (kb23.y + eb23.y);

        pa += __shfl_xor_sync(0xffffffffu, pa, 1);
        pb += __shfl_xor_sync(0xffffffffu, pb, 1);
        pa += __shfl_xor_sync(0xffffffffu, pa, 2);
        pb += __shfl_xor_sync(0xffffffffu, pb, 2);
        pa += __shfl_xor_sync(0xffffffffu, pa, 4);
        pb += __shfl_xor_sync(0xffffffffu, pb, 4);

        float aa = pa * isc;
        float ab = has2 ? (pb * isc) : -1e30f;

        float nm = fmaxf(m, fmaxf(aa, ab));
        float sc = __expf(m - nm);
        float wa = __expf(aa - nm);
        float wb = __expf(ab - nm);           // 0 when !has2
        den = den * sc + wa + wb;
        acc0 = acc0 * sc + wa * (va01.x + ea01.x) + wb * (vb01.x + eb01.x);
        acc1 = acc1 * sc + wa * (va01.y + ea01.y) + wb * (vb01.y + eb01.y);
        acc2 = acc2 * sc + wa * (va23.x + ea23.x) + wb * (vb23.x + eb23.x);
        acc3 = acc3 * sc + wa * (va23.y + ea23.y) + wb * (vb23.y + eb23.y);
        m = nm;
    }

    float inv = 1.f / (den + 1e-16f);
    uint2 skr = *(const uint2*)(g_skip + n * HC + c0);
    float2 s01 = __half22float2(*(__half2*)&skr.x);
    float2 s23 = __half22float2(*(__half2*)&skr.y);
    *(float4*)(out + n * HC + c0) =
        make_float4(acc0 * inv + s01.x, acc1 * inv + s01.y,
                    acc2 * inv + s23.x, acc3 * inv + s23.y);
}

// ----------------------------- launch -----------------------------------------
extern "C" void kernel_launch(void* const* d_in, const int* in_sizes, int n_in,
                              void* d_out, int out_size)
{
    const float* x   = (const float*)d_in[0];
    const int*   ei  = (const int*)d_in[1];
    const float* ea  = (const float*)d_in[2];
    const float* Wq  = (const float*)d_in[3];
    const float* bq  = (const float*)d_in[4];
    const float* Wk  = (const float*)d_in[5];
    const float* bk  = (const float*)d_in[6];
    const float* Wv  = (const float*)d_in[7];
    const float* bv  = (const float*)d_in[8];
    const float* We  = (const float*)d_in[9];
    const float* Wsk = (const float*)d_in[10];
    const float* bsk = (const float*)d_in[11];
    float* out = (float*)d_out;

    const int smem_fused = (64 * NSTR + 128 * NSTR) * 2;   // 52.2 KB (max of both)
    cudaFuncSetAttribute(gemm_fused_kernel,
                         cudaFuncAttributeMaxDynamicSharedMemorySize, smem_fused);

    prep_weights_kernel<<<128, 256>>>(Wq, Wk, Wv, Wsk, We);          // #1
    count_kernel<<<E_EDGES / 256, 256>>>(ei);                        // #2
    scan1_kernel<<<SCAN_B, 256>>>();                                 // #3
    gemm_fused_kernel<<<NP_BLOCKS + EG_BLOCKS, 256, smem_fused>>>(   // #4 (profiled)
        x, ea, bq, bk, bv, bsk);
    scan2_kernel<<<1, 256>>>();                                      // #5
    scan3_kernel<<<SCAN_B, 256>>>();                                 // #6
    fill_kernel<<<E_EDGES / 256, 256>>>(ei);                         // #7
    agg_fused_kernel<<<(N_NODES * 32) / 256, 256>>>(out);            // #8
}